// round 4
// baseline (speedup 1.0000x reference)
#include <cuda_runtime.h>
#include <math.h>
#include <cstdint>

#define NB 64
#define NL 64
#define ND 512

// ---------------- device scratch (allocation-free rule) ----------------
__device__ float g_G[NB * NL * NL];     // Gram per j
__device__ float g_w1[NB * NL];         // ||sent[i,q]||
__device__ float g_sim[NB * NB];        // g_sim[j*64+i]
__device__ float g_S[4096u * 4096u];    // scores: row = sent flat (i*64+q), col = ecg flat (j*64+s)

// ---------------- helpers ----------------
__device__ __forceinline__ uint32_t smem_u32(const void* p) {
    uint32_t a;
    asm("{ .reg .u64 t; cvta.to.shared.u64 t, %1; cvt.u32.u64 %0, t; }" : "=r"(a) : "l"(p));
    return a;
}
__device__ __forceinline__ float tf32r(float x) {
    float r;
    asm("cvt.rna.tf32.f32 %0, %1;" : "=f"(r) : "f"(x));
    return r;
}
__device__ __forceinline__ void lds64(uint32_t& x, uint32_t& y, uint32_t a) {
    asm volatile("ld.shared.v2.b32 {%0, %1}, [%2];" : "=r"(x), "=r"(y) : "r"(a));
}
__device__ __forceinline__ void sts64(uint32_t a, float x, float y) {
    asm volatile("st.shared.v2.f32 [%0], {%1, %2};" :: "r"(a), "f"(x), "f"(y) : "memory");
}
__device__ __forceinline__ void mma_tf32(float* c, const uint32_t* a, const uint32_t* b) {
    asm volatile(
        "mma.sync.aligned.m16n8k8.row.col.f32.tf32.tf32.f32 "
        "{%0,%1,%2,%3}, {%4,%5,%6,%7}, {%8,%9}, {%0,%1,%2,%3};"
        : "+f"(c[0]), "+f"(c[1]), "+f"(c[2]), "+f"(c[3])
        : "r"(a[0]), "r"(a[1]), "r"(a[2]), "r"(a[3]), "r"(b[0]), "r"(b[1]));
}

// FMA-pipe exp: exp(x) for x <= 0 (clamped at -87), rel err ~1e-7.
// Uses magic-number round-to-nearest for 2^n extraction; no MUFU, no F2I.
__device__ __forceinline__ float fexp(float x) {
    x = fmaxf(x, -87.0f);
    float t = fmaf(x, 1.4426950408889634f, 12582912.0f);  // 1.5*2^23
    float n = t - 12582912.0f;
    float f = fmaf(x, 1.4426950408889634f, -n);           // f in [-0.5, 0.5]
    float p = 1.33978935e-3f;
    p = fmaf(p, f, 9.67518295e-3f);
    p = fmaf(p, f, 5.55041086e-2f);
    p = fmaf(p, f, 2.40226507e-1f);
    p = fmaf(p, f, 6.93147182e-1f);
    p = fmaf(p, f, 1.0f);
    int ni = __float_as_int(t) - 0x4B400000;
    float s = __int_as_float((ni + 127) << 23);
    return p * s;
}

// ===========================================================================
// Kernel A: S = sent(4096x512) @ ecg(4096x512)^T via 3xTF32 mma.sync
// (unchanged from R3 — inferred fast)
// ===========================================================================
#define BK 32
#define NCH (ND / BK)
#define ROWW 40u
#define TILE_WORDS (128u * ROWW)
#define OFF_AHI 0u
#define OFF_ALO (TILE_WORDS * 4u)
#define OFF_BHI (TILE_WORDS * 8u)
#define OFF_BLO (TILE_WORDS * 12u)
#define STAGE_B (TILE_WORDS * 16u)
#define SMEM_TOTAL (2u * STAGE_B)

__global__ __launch_bounds__(256, 1) void s_gemm_kernel(const float* __restrict__ ecg,
                                                        const float* __restrict__ sent) {
    extern __shared__ char dsm[];
    const uint32_t sbase = smem_u32(dsm);

    const int tid = threadIdx.x;
    const int wid = tid >> 5, lane = tid & 31;
    const int tileN = blockIdx.x;
    const int tileM = blockIdx.y;

    const int grow = tid >> 1;
    const int gcb = (tid & 1) * 16;
    const float* Ag = sent + ((size_t)tileM * 128 + grow) * ND + gcb;
    const float* Bg = ecg + ((size_t)tileN * 128 + grow) * ND + gcb;

    uint32_t stsw[8];
#pragma unroll
    for (int g2 = 0; g2 < 2; ++g2)
#pragma unroll
        for (int d = 0; d < 4; ++d)
            stsw[g2 * 4 + d] = (uint32_t)grow * ROWW + (uint32_t)(((gcb >> 3) + g2) * 8 + 2 * d);

    const uint32_t warpM = (uint32_t)(wid & 1) * 64u;
    const uint32_t warpN = (uint32_t)(wid >> 1) * 32u;
    const uint32_t lg = lane >> 2, lt = lane & 3;

    float acc[4][4][4];
#pragma unroll
    for (int mi = 0; mi < 4; ++mi)
#pragma unroll
        for (int ni = 0; ni < 4; ++ni)
#pragma unroll
            for (int r = 0; r < 4; ++r) acc[mi][ni][r] = 0.f;

    float4 ra[4], rb[4];
#pragma unroll
    for (int r = 0; r < 4; ++r) {
        ra[r] = *reinterpret_cast<const float4*>(Ag + r * 4);
        rb[r] = *reinterpret_cast<const float4*>(Bg + r * 4);
    }

    auto sts_chunk = [&](uint32_t st) {
        float v[16];
#pragma unroll
        for (int r = 0; r < 4; ++r) {
            v[r * 4 + 0] = ra[r].x; v[r * 4 + 1] = ra[r].y;
            v[r * 4 + 2] = ra[r].z; v[r * 4 + 3] = ra[r].w;
        }
#pragma unroll
        for (int p = 0; p < 8; ++p) {
            int g2 = p >> 2, d = p & 3;
            float x = v[g2 * 8 + d], y = v[g2 * 8 + d + 4];
            float hx = tf32r(x), hy = tf32r(y);
            uint32_t a = st + stsw[p] * 4u;
            sts64(a + OFF_AHI, hx, hy);
            sts64(a + OFF_ALO, tf32r(x - hx), tf32r(y - hy));
        }
#pragma unroll
        for (int r = 0; r < 4; ++r) {
            v[r * 4 + 0] = rb[r].x; v[r * 4 + 1] = rb[r].y;
            v[r * 4 + 2] = rb[r].z; v[r * 4 + 3] = rb[r].w;
        }
#pragma unroll
        for (int p = 0; p < 8; ++p) {
            int g2 = p >> 2, d = p & 3;
            float x = v[g2 * 8 + d], y = v[g2 * 8 + d + 4];
            float hx = tf32r(x), hy = tf32r(y);
            uint32_t a = st + stsw[p] * 4u;
            sts64(a + OFF_BHI, hx, hy);
            sts64(a + OFF_BLO, tf32r(x - hx), tf32r(y - hy));
        }
    };

    sts_chunk(sbase);
    __syncthreads();

    for (int t = 0; t < NCH; ++t) {
        const uint32_t st = sbase + (uint32_t)(t & 1) * STAGE_B;
        if (t + 1 < NCH) {
#pragma unroll
            for (int r = 0; r < 4; ++r) {
                ra[r] = *reinterpret_cast<const float4*>(Ag + (t + 1) * BK + r * 4);
                rb[r] = *reinterpret_cast<const float4*>(Bg + (t + 1) * BK + r * 4);
            }
        }
#pragma unroll
        for (int k8 = 0; k8 < 4; ++k8) {
            uint32_t ah[4][4], al[4][4], bh[4][2], bl[4][2];
            const uint32_t kw = (uint32_t)k8 * 8u + 2u * lt;
#pragma unroll
            for (int mi = 0; mi < 4; ++mi) {
                uint32_t r0 = (warpM + mi * 16u + lg) * ROWW + kw;
                uint32_t r1 = r0 + 8u * ROWW;
                lds64(ah[mi][0], ah[mi][2], st + OFF_AHI + r0 * 4u);
                lds64(ah[mi][1], ah[mi][3], st + OFF_AHI + r1 * 4u);
                lds64(al[mi][0], al[mi][2], st + OFF_ALO + r0 * 4u);
                lds64(al[mi][1], al[mi][3], st + OFF_ALO + r1 * 4u);
            }
#pragma unroll
            for (int ni = 0; ni < 4; ++ni) {
                uint32_t r0 = (warpN + ni * 8u + lg) * ROWW + kw;
                lds64(bh[ni][0], bh[ni][1], st + OFF_BHI + r0 * 4u);
                lds64(bl[ni][0], bl[ni][1], st + OFF_BLO + r0 * 4u);
            }
#pragma unroll
            for (int mi = 0; mi < 4; ++mi)
#pragma unroll
                for (int ni = 0; ni < 4; ++ni) {
                    mma_tf32(acc[mi][ni], ah[mi], bh[ni]);
                    mma_tf32(acc[mi][ni], ah[mi], bl[ni]);
                    mma_tf32(acc[mi][ni], al[mi], bh[ni]);
                }
        }
        if (t + 1 < NCH) sts_chunk(sbase + (uint32_t)((t + 1) & 1) * STAGE_B);
        __syncthreads();
    }

    const size_t rbase = (size_t)tileM * 128 + warpM + lg;
    const size_t cbase = (size_t)tileN * 128 + warpN + lt * 2;
#pragma unroll
    for (int mi = 0; mi < 4; ++mi)
#pragma unroll
        for (int ni = 0; ni < 4; ++ni) {
            float* p0 = g_S + (rbase + mi * 16) * 4096u + cbase + ni * 8;
            *reinterpret_cast<float2*>(p0) = make_float2(acc[mi][ni][0], acc[mi][ni][1]);
            *reinterpret_cast<float2*>(p0 + 8 * 4096u) = make_float2(acc[mi][ni][2], acc[mi][ni][3]);
        }
}

// ===========================================================================
// Kernel B: Gram quadrants (256 CTAs) + w1 norms. (unchanged)
// ===========================================================================
__global__ __launch_bounds__(256) void gram_kernel(const float* __restrict__ ecg,
                                                   const float* __restrict__ sent) {
    __shared__ float sA[32 * 66];
    __shared__ float sB[32 * 66];
    const int j = blockIdx.x >> 2;
    const int quad = blockIdx.x & 3;
    const int qr = (quad >> 1) * 32, qc = (quad & 1) * 32;
    const int tid = threadIdx.x;
    const int tx = tid & 15, ty = tid >> 4;
    const int r0 = ty * 2, c0 = tx * 2;
    const float* base = ecg + (size_t)j * NL * ND;

    float c00 = 0.f, c01 = 0.f, c10 = 0.f, c11 = 0.f;
    const int lrow = tid >> 3;
    const int lcol = (tid & 7) * 8;

    for (int kt = 0; kt < ND; kt += 64) {
        __syncthreads();
#pragma unroll
        for (int r = 0; r < 2; ++r) {
            float4 va = *reinterpret_cast<const float4*>(base + (qr + lrow) * ND + kt + lcol + r * 4);
            sA[lrow * 66 + lcol + r * 4 + 0] = va.x;
            sA[lrow * 66 + lcol + r * 4 + 1] = va.y;
            sA[lrow * 66 + lcol + r * 4 + 2] = va.z;
            sA[lrow * 66 + lcol + r * 4 + 3] = va.w;
            float4 vb = *reinterpret_cast<const float4*>(base + (qc + lrow) * ND + kt + lcol + r * 4);
            sB[lrow * 66 + lcol + r * 4 + 0] = vb.x;
            sB[lrow * 66 + lcol + r * 4 + 1] = vb.y;
            sB[lrow * 66 + lcol + r * 4 + 2] = vb.z;
            sB[lrow * 66 + lcol + r * 4 + 3] = vb.w;
        }
        __syncthreads();
#pragma unroll 8
        for (int k = 0; k < 64; ++k) {
            float a0 = sA[r0 * 66 + k], a1 = sA[(r0 + 1) * 66 + k];
            float b0 = sB[c0 * 66 + k], b1 = sB[(c0 + 1) * 66 + k];
            c00 = fmaf(a0, b0, c00);
            c01 = fmaf(a0, b1, c01);
            c10 = fmaf(a1, b0, c10);
            c11 = fmaf(a1, b1, c11);
        }
    }
    float* Gp = g_G + (size_t)j * NL * NL;
    Gp[(qr + r0) * NL + qc + c0] = c00;
    Gp[(qr + r0) * NL + qc + c0 + 1] = c01;
    Gp[(qr + r0 + 1) * NL + qc + c0] = c10;
    Gp[(qr + r0 + 1) * NL + qc + c0 + 1] = c11;

    if (quad == 0) {
        int q = tid >> 2;
        int p = tid & 3;
        const float* sp = sent + (size_t)j * NL * ND + q * ND + p * 128;
        float s = 0.f;
#pragma unroll 8
        for (int t2 = 0; t2 < 32; t2++) {
            float4 v = *reinterpret_cast<const float4*>(sp + t2 * 4);
            s = fmaf(v.x, v.x, fmaf(v.y, v.y, fmaf(v.z, v.z, fmaf(v.w, v.w, s))));
        }
        s += __shfl_xor_sync(0xffffffffu, s, 1);
        s += __shfl_xor_sync(0xffffffffu, s, 2);
        if (p == 0) g_w1[j * NL + q] = sqrtf(s);
    }
}

// ===========================================================================
// Kernel C: per-pair epilogue. exp count: 32/thread (deduped), all on FMA pipe.
// ===========================================================================
__global__ __launch_bounds__(256) void pair_kernel(float* __restrict__ out) {
    __shared__ float Ah[64 * 66];
    __shared__ float Gh[64 * 65];
    __shared__ float pbuf[16 * 68];
    __shared__ float colm[64], crZ[64], rowm[64], rrZ[64], esum[64];

    const int i = blockIdx.x, j = blockIdx.y;
    const int tid = threadIdx.x;
    const int tx = tid & 15, ty = tid >> 4;
    const int row0 = ty * 4, col0 = tx * 4;

    float c[4][4];
    const float* Sp = g_S + ((size_t)i * 64) * 4096u + (size_t)j * 64;
#pragma unroll
    for (int m = 0; m < 4; m++) {
        float4 v4 = *reinterpret_cast<const float4*>(Sp + (size_t)(row0 + m) * 4096u + col0);
        c[m][0] = v4.x; c[m][1] = v4.y; c[m][2] = v4.z; c[m][3] = v4.w;
    }
    {
        const float* Gp = g_G + (size_t)j * NL * NL;
        int f = (tid & 15) * 4;
        int q0 = tid >> 4;
#pragma unroll
        for (int r = 0; r < 4; ++r) {
            int q = q0 + r * 16;
            float4 g = *reinterpret_cast<const float4*>(Gp + q * NL + f);
            Gh[q * 65 + f + 0] = g.x;
            Gh[q * 65 + f + 1] = g.y;
            Gh[q * 65 + f + 2] = g.z;
            Gh[q * 65 + f + 3] = g.w;
        }
    }

    // ---- column max (softmax over q, per column s) ----
#pragma unroll
    for (int n = 0; n < 4; n++) {
        float pm = c[0][n];
#pragma unroll
        for (int m = 1; m < 4; m++) pm = fmaxf(pm, c[m][n]);
        pbuf[ty * 68 + col0 + n] = pm;
    }
    __syncthreads();
    if (tid < 64) {
        float m = -1e30f;
#pragma unroll
        for (int p = 0; p < 16; p++) m = fmaxf(m, pbuf[p * 68 + tid]);
        colm[tid] = m;
    }
    __syncthreads();

    // ---- e1 = exp(c - colm) ONCE; column sums ----
    float v[4][4];
#pragma unroll
    for (int n = 0; n < 4; n++) {
        float cm = colm[col0 + n];
        float s = 0.f;
#pragma unroll
        for (int m = 0; m < 4; m++) {
            float e = fexp(c[m][n] - cm);
            v[m][n] = e;
            s += e;
        }
        pbuf[ty * 68 + col0 + n] = s;
    }
    __syncthreads();
    if (tid < 64) {
        float z = 0.f;
#pragma unroll
        for (int p = 0; p < 16; p++) z += pbuf[p * 68 + tid];
        crZ[tid] = 4.f / z;   // fold TEMP1=4 into the normalization
    }
    __syncthreads();

    // ---- V = 4 * A1^T (scale e1); row max ----
#pragma unroll
    for (int n = 0; n < 4; n++) {
        float zr = crZ[col0 + n];
#pragma unroll
        for (int m = 0; m < 4; m++) v[m][n] *= zr;
    }
#pragma unroll
    for (int m = 0; m < 4; m++) {
        float pm = v[m][0];
#pragma unroll
        for (int n = 1; n < 4; n++) pm = fmaxf(pm, v[m][n]);
        pbuf[tx * 68 + row0 + m] = pm;
    }
    __syncthreads();
    if (tid < 64) {
        float m = -1e30f;
#pragma unroll
        for (int p = 0; p < 16; p++) m = fmaxf(m, pbuf[p * 68 + tid]);
        rowm[tid] = m;
    }
    __syncthreads();

    // ---- e2 = exp(v - rowm) ONCE; row sums ----
#pragma unroll
    for (int m = 0; m < 4; m++) {
        float rm = rowm[row0 + m];
        float s = 0.f;
#pragma unroll
        for (int n = 0; n < 4; n++) {
            float e = fexp(v[m][n] - rm);
            v[m][n] = e;
            s += e;
        }
        pbuf[tx * 68 + row0 + m] = s;
    }
    __syncthreads();
    if (tid < 64) {
        float z = 0.f;
#pragma unroll
        for (int p = 0; p < 16; p++) z += pbuf[p * 68 + tid];
        rrZ[tid] = 1.f / z;
    }
    __syncthreads();

    // ---- A2 = e2 * rrZ ; w12 partials ----
#pragma unroll
    for (int m = 0; m < 4; m++) {
        float zr = rrZ[row0 + m];
        float w12p = 0.f;
#pragma unroll
        for (int n = 0; n < 4; n++) {
            float a2 = v[m][n] * zr;
            v[m][n] = a2;
            w12p = fmaf(a2, c[m][n], w12p);
        }
        pbuf[tx * 68 + row0 + m] = w12p;
    }
    __syncthreads();
    float my_w12 = 0.f;
    if (tid < 64) {
#pragma unroll
        for (int p = 0; p < 16; p++) my_w12 += pbuf[p * 68 + tid];
    }

#pragma unroll
    for (int m = 0; m < 4; m++)
#pragma unroll
        for (int n = 0; n < 4; n++) Ah[(row0 + m) * 66 + col0 + n] = v[m][n];
    __syncthreads();

    // ---- GEMM2: T = A2 @ G_j ; w2^2 partials ----
    float t4[4][4];
#pragma unroll
    for (int m = 0; m < 4; m++)
#pragma unroll
        for (int n = 0; n < 4; n++) t4[m][n] = 0.f;
#pragma unroll 8
    for (int k = 0; k < 64; k++) {
        float a[4], g[4];
#pragma unroll
        for (int m = 0; m < 4; m++) a[m] = Ah[(row0 + m) * 66 + k];
#pragma unroll
        for (int n = 0; n < 4; n++) g[n] = Gh[k * 65 + col0 + n];
#pragma unroll
        for (int m = 0; m < 4; m++)
#pragma unroll
            for (int n = 0; n < 4; n++) t4[m][n] = fmaf(a[m], g[n], t4[m][n]);
    }
    __syncthreads();
#pragma unroll
    for (int m = 0; m < 4; m++) {
        float w2p = 0.f;
#pragma unroll
        for (int n = 0; n < 4; n++) w2p = fmaf(t4[m][n], v[m][n], w2p);
        pbuf[tx * 68 + row0 + m] = w2p;
    }
    __syncthreads();

    if (tid < 64) {
        float w2sq = 0.f;
#pragma unroll
        for (int p = 0; p < 16; p++) w2sq += pbuf[p * 68 + tid];
        float w2 = sqrtf(fmaxf(w2sq, 0.f));
        float den = fmaxf(g_w1[i * NL + tid] * w2, 1e-8f);
        float cs = my_w12 / den;
        esum[tid] = __expf(5.f * cs);   // only 64 MUFU-exps per CTA; negligible
    }
    __syncthreads();
    if (tid == 0) {
        float z = 0.f;
#pragma unroll
        for (int q = 0; q < 64; q++) z += esum[q];
        g_sim[j * NB + i] = 10.f * logf(z);
    }

    if (i == j) {
        float* ap = out + 1 + (size_t)i * NL * NL;
#pragma unroll
        for (int m = 0; m < 4; m++)
#pragma unroll
            for (int n = 0; n < 4; n++)
                ap[(row0 + m) * NL + col0 + n] = v[m][n];
    }
}

// ===========================================================================
// Kernel D: symmetric InfoNCE loss; g_sim staged to smem.
// ===========================================================================
__global__ __launch_bounds__(256) void loss_kernel(float* __restrict__ out) {
    __shared__ float sm[64 * 64];
    __shared__ float sh[64];
    const int tid = threadIdx.x;
#pragma unroll
    for (int r = 0; r < 4; ++r) {
        int idx = tid * 4 + r * 1024;
        *reinterpret_cast<float4*>(sm + idx) = *reinterpret_cast<const float4*>(g_sim + idx);
    }
    __syncthreads();
    if (tid < 64) {
        int t = tid;
        float m1 = -1e30f, m2 = -1e30f;
#pragma unroll 8
        for (int b = 0; b < NB; b++) {
            m1 = fmaxf(m1, sm[t * NB + b]);
            m2 = fmaxf(m2, sm[b * NB + t]);
        }
        float z1 = 0.f, z2 = 0.f;
#pragma unroll 8
        for (int b = 0; b < NB; b++) {
            z1 += fexp(sm[t * NB + b] - m1);
            z2 += fexp(sm[b * NB + t] - m2);
        }
        float dg = sm[t * NB + t];
        sh[t] = (dg - (m1 + logf(z1))) + (dg - (m2 + logf(z2)));
    }
    __syncthreads();
    if (tid == 0) {
        float s = 0.f;
#pragma unroll
        for (int q = 0; q < NB; q++) s += sh[q];
        out[0] = -s / (2.f * (float)NB);
    }
}

extern "C" void kernel_launch(void* const* d_in, const int* in_sizes, int n_in,
                              void* d_out, int out_size) {
    const float* ecg = (const float*)d_in[0];   // (64,64,512)
    const float* sent = (const float*)d_in[1];  // (64,64,512)
    float* out = (float*)d_out;                 // [loss, att_maps]

    cudaFuncSetAttribute(s_gemm_kernel, cudaFuncAttributeMaxDynamicSharedMemorySize, SMEM_TOTAL);

    s_gemm_kernel<<<dim3(32, 32), 256, SMEM_TOTAL>>>(ecg, sent);
    gram_kernel<<<256, 256>>>(ecg, sent);
    pair_kernel<<<dim3(64, 64), 256>>>(out);
    loss_kernel<<<1, 256>>>(out);
}

// round 5
// speedup vs baseline: 1.1029x; 1.1029x over previous
#include <cuda_runtime.h>
#include <math.h>
#include <cstdint>

#define NB 64
#define NL 64
#define ND 512

// ---------------- device scratch (allocation-free rule) ----------------
__device__ float g_G[NB * NL * NL];     // Gram per j
__device__ float g_w1[NB * NL];         // ||sent[i,q]||
__device__ float g_sim[NB * NB];        // g_sim[j*64+i]
__device__ float g_S[4096u * 4096u];    // scores

// ---------------- helpers ----------------
__device__ __forceinline__ uint32_t smem_u32(const void* p) {
    uint32_t a;
    asm("{ .reg .u64 t; cvta.to.shared.u64 t, %1; cvt.u32.u64 %0, t; }" : "=r"(a) : "l"(p));
    return a;
}
__device__ __forceinline__ float tf32r(float x) {
    float r;
    asm("cvt.rna.tf32.f32 %0, %1;" : "=f"(r) : "f"(x));
    return r;
}
__device__ __forceinline__ void lds64(uint32_t& x, uint32_t& y, uint32_t a) {
    asm volatile("ld.shared.v2.b32 {%0, %1}, [%2];" : "=r"(x), "=r"(y) : "r"(a));
}
__device__ __forceinline__ void sts64(uint32_t a, float x, float y) {
    asm volatile("st.shared.v2.f32 [%0], {%1, %2};" :: "r"(a), "f"(x), "f"(y) : "memory");
}
__device__ __forceinline__ void mma_tf32(float* c, const uint32_t* a, const uint32_t* b) {
    asm volatile(
        "mma.sync.aligned.m16n8k8.row.col.f32.tf32.tf32.f32 "
        "{%0,%1,%2,%3}, {%4,%5,%6,%7}, {%8,%9}, {%0,%1,%2,%3};"
        : "+f"(c[0]), "+f"(c[1]), "+f"(c[2]), "+f"(c[3])
        : "r"(a[0]), "r"(a[1]), "r"(a[2]), "r"(a[3]), "r"(b[0]), "r"(b[1]));
}

// FMA-pipe exp for x <= 0 (clamped at -87), rel err ~1e-7.
__device__ __forceinline__ float fexp(float x) {
    x = fmaxf(x, -87.0f);
    float t = fmaf(x, 1.4426950408889634f, 12582912.0f);
    float n = t - 12582912.0f;
    float f = fmaf(x, 1.4426950408889634f, -n);
    float p = 1.33978935e-3f;
    p = fmaf(p, f, 9.67518295e-3f);
    p = fmaf(p, f, 5.55041086e-2f);
    p = fmaf(p, f, 2.40226507e-1f);
    p = fmaf(p, f, 6.93147182e-1f);
    p = fmaf(p, f, 1.0f);
    int ni = __float_as_int(t) - 0x4B400000;
    float s = __int_as_float((ni + 127) << 23);
    return p * s;
}

// ===========================================================================
// Kernel A: S = sent(4096x512) @ ecg(4096x512)^T via 3xTF32 mma.sync
//   Conflict-free STS via per-row slot rotation; STS/LDG overlapped with MMA.
// ===========================================================================
#define BK 32
#define NCH (ND / BK)
#define ROWW 40u
#define TILE_WORDS (128u * ROWW)
#define OFF_AHI 0u
#define OFF_ALO (TILE_WORDS * 4u)
#define OFF_BHI (TILE_WORDS * 8u)
#define OFF_BLO (TILE_WORDS * 12u)
#define STAGE_B (TILE_WORDS * 16u)
#define SMEM_TOTAL (2u * STAGE_B)

__global__ __launch_bounds__(256, 1) void s_gemm_kernel(const float* __restrict__ ecg,
                                                        const float* __restrict__ sent) {
    extern __shared__ char dsm[];
    const uint32_t sbase = smem_u32(dsm);

    const int tid = threadIdx.x;
    const int wid = tid >> 5, lane = tid & 31;
    const int tileN = blockIdx.x;
    const int tileM = blockIdx.y;

    const int grow = tid >> 1;
    const int gcb = (tid & 1) * 16;
    const float* Ag = sent + ((size_t)tileM * 128 + grow) * ND + gcb;
    const float* Bg = ecg + ((size_t)tileN * 128 + grow) * ND + gcb;

    // STS word offsets with per-row slot rotation: slot = (d + (grow>>1)) & 3
    uint32_t stsw[8];
#pragma unroll
    for (int g2 = 0; g2 < 2; ++g2)
#pragma unroll
        for (int d = 0; d < 4; ++d) {
            int slot = (d + ((grow >> 1) & 3)) & 3;
            stsw[g2 * 4 + d] = (uint32_t)grow * ROWW + (uint32_t)(((gcb >> 3) + g2) * 8 + 2 * slot);
        }

    const uint32_t warpM = (uint32_t)(wid & 1) * 64u;
    const uint32_t warpN = (uint32_t)(wid >> 1) * 32u;
    const uint32_t lg = lane >> 2, lt = lane & 3;
    // fragment column offset with matching rotation (words)
    const uint32_t ltr = 2u * ((lt + (lg >> 1)) & 3u);

    float acc[4][4][4];
#pragma unroll
    for (int mi = 0; mi < 4; ++mi)
#pragma unroll
        for (int ni = 0; ni < 4; ++ni)
#pragma unroll
            for (int r = 0; r < 4; ++r) acc[mi][ni][r] = 0.f;

    float4 ra[4], rb[4];

    auto ldg_chunk = [&](int t) {
#pragma unroll
        for (int r = 0; r < 4; ++r) {
            ra[r] = *reinterpret_cast<const float4*>(Ag + t * BK + r * 4);
            rb[r] = *reinterpret_cast<const float4*>(Bg + t * BK + r * 4);
        }
    };

    auto sts_chunk = [&](uint32_t st) {
        float v[16];
#pragma unroll
        for (int r = 0; r < 4; ++r) {
            v[r * 4 + 0] = ra[r].x; v[r * 4 + 1] = ra[r].y;
            v[r * 4 + 2] = ra[r].z; v[r * 4 + 3] = ra[r].w;
        }
#pragma unroll
        for (int p = 0; p < 8; ++p) {
            int g2 = p >> 2, d = p & 3;
            float x = v[g2 * 8 + d], y = v[g2 * 8 + d + 4];
            float hx = tf32r(x), hy = tf32r(y);
            uint32_t a = st + stsw[p] * 4u;
            sts64(a + OFF_AHI, hx, hy);
            sts64(a + OFF_ALO, tf32r(x - hx), tf32r(y - hy));
        }
#pragma unroll
        for (int r = 0; r < 4; ++r) {
            v[r * 4 + 0] = rb[r].x; v[r * 4 + 1] = rb[r].y;
            v[r * 4 + 2] = rb[r].z; v[r * 4 + 3] = rb[r].w;
        }
#pragma unroll
        for (int p = 0; p < 8; ++p) {
            int g2 = p >> 2, d = p & 3;
            float x = v[g2 * 8 + d], y = v[g2 * 8 + d + 4];
            float hx = tf32r(x), hy = tf32r(y);
            uint32_t a = st + stsw[p] * 4u;
            sts64(a + OFF_BHI, hx, hy);
            sts64(a + OFF_BLO, tf32r(x - hx), tf32r(y - hy));
        }
    };

    // prologue: chunk0 -> buf0; chunk1 staged in regs
    ldg_chunk(0);
    sts_chunk(sbase);
    ldg_chunk(1);
    __syncthreads();

    for (int t = 0; t < NCH; ++t) {
        const uint32_t st = sbase + (uint32_t)(t & 1) * STAGE_B;
        // overlap: stage chunk t+1 into the other buffer, start LDG for t+2
        if (t + 1 < NCH) sts_chunk(sbase + (uint32_t)((t + 1) & 1) * STAGE_B);
        if (t + 2 < NCH) ldg_chunk(t + 2);

#pragma unroll
        for (int k8 = 0; k8 < 4; ++k8) {
            uint32_t ah[4][4], al[4][4], bh[4][2], bl[4][2];
            const uint32_t kw = (uint32_t)k8 * 8u + ltr;
#pragma unroll
            for (int mi = 0; mi < 4; ++mi) {
                uint32_t r0 = (warpM + mi * 16u + lg) * ROWW + kw;
                uint32_t r1 = r0 + 8u * ROWW;
                lds64(ah[mi][0], ah[mi][2], st + OFF_AHI + r0 * 4u);
                lds64(ah[mi][1], ah[mi][3], st + OFF_AHI + r1 * 4u);
                lds64(al[mi][0], al[mi][2], st + OFF_ALO + r0 * 4u);
                lds64(al[mi][1], al[mi][3], st + OFF_ALO + r1 * 4u);
            }
#pragma unroll
            for (int ni = 0; ni < 4; ++ni) {
                uint32_t r0 = (warpN + ni * 8u + lg) * ROWW + kw;
                lds64(bh[ni][0], bh[ni][1], st + OFF_BHI + r0 * 4u);
                lds64(bl[ni][0], bl[ni][1], st + OFF_BLO + r0 * 4u);
            }
#pragma unroll
            for (int mi = 0; mi < 4; ++mi)
#pragma unroll
                for (int ni = 0; ni < 4; ++ni) {
                    mma_tf32(acc[mi][ni], ah[mi], bh[ni]);
                    mma_tf32(acc[mi][ni], ah[mi], bl[ni]);
                    mma_tf32(acc[mi][ni], al[mi], bh[ni]);
                }
        }
        __syncthreads();
    }

    const size_t rbase = (size_t)tileM * 128 + warpM + lg;
    const size_t cbase = (size_t)tileN * 128 + warpN + lt * 2;
#pragma unroll
    for (int mi = 0; mi < 4; ++mi)
#pragma unroll
        for (int ni = 0; ni < 4; ++ni) {
            float* p0 = g_S + (rbase + mi * 16) * 4096u + cbase + ni * 8;
            *reinterpret_cast<float2*>(p0) = make_float2(acc[mi][ni][0], acc[mi][ni][1]);
            *reinterpret_cast<float2*>(p0 + 8 * 4096u) = make_float2(acc[mi][ni][2], acc[mi][ni][3]);
        }
}

// ===========================================================================
// Kernel B: Gram quadrants (256 CTAs) + w1 norms. (unchanged)
// ===========================================================================
__global__ __launch_bounds__(256) void gram_kernel(const float* __restrict__ ecg,
                                                   const float* __restrict__ sent) {
    __shared__ float sA[32 * 66];
    __shared__ float sB[32 * 66];
    const int j = blockIdx.x >> 2;
    const int quad = blockIdx.x & 3;
    const int qr = (quad >> 1) * 32, qc = (quad & 1) * 32;
    const int tid = threadIdx.x;
    const int tx = tid & 15, ty = tid >> 4;
    const int r0 = ty * 2, c0 = tx * 2;
    const float* base = ecg + (size_t)j * NL * ND;

    float c00 = 0.f, c01 = 0.f, c10 = 0.f, c11 = 0.f;
    const int lrow = tid >> 3;
    const int lcol = (tid & 7) * 8;

    for (int kt = 0; kt < ND; kt += 64) {
        __syncthreads();
#pragma unroll
        for (int r = 0; r < 2; ++r) {
            float4 va = *reinterpret_cast<const float4*>(base + (qr + lrow) * ND + kt + lcol + r * 4);
            sA[lrow * 66 + lcol + r * 4 + 0] = va.x;
            sA[lrow * 66 + lcol + r * 4 + 1] = va.y;
            sA[lrow * 66 + lcol + r * 4 + 2] = va.z;
            sA[lrow * 66 + lcol + r * 4 + 3] = va.w;
            float4 vb = *reinterpret_cast<const float4*>(base + (qc + lrow) * ND + kt + lcol + r * 4);
            sB[lrow * 66 + lcol + r * 4 + 0] = vb.x;
            sB[lrow * 66 + lcol + r * 4 + 1] = vb.y;
            sB[lrow * 66 + lcol + r * 4 + 2] = vb.z;
            sB[lrow * 66 + lcol + r * 4 + 3] = vb.w;
        }
        __syncthreads();
#pragma unroll 8
        for (int k = 0; k < 64; ++k) {
            float a0 = sA[r0 * 66 + k], a1 = sA[(r0 + 1) * 66 + k];
            float b0 = sB[c0 * 66 + k], b1 = sB[(c0 + 1) * 66 + k];
            c00 = fmaf(a0, b0, c00);
            c01 = fmaf(a0, b1, c01);
            c10 = fmaf(a1, b0, c10);
            c11 = fmaf(a1, b1, c11);
        }
    }
    float* Gp = g_G + (size_t)j * NL * NL;
    Gp[(qr + r0) * NL + qc + c0] = c00;
    Gp[(qr + r0) * NL + qc + c0 + 1] = c01;
    Gp[(qr + r0 + 1) * NL + qc + c0] = c10;
    Gp[(qr + r0 + 1) * NL + qc + c0 + 1] = c11;

    if (quad == 0) {
        int q = tid >> 2;
        int p = tid & 3;
        const float* sp = sent + (size_t)j * NL * ND + q * ND + p * 128;
        float s = 0.f;
#pragma unroll 8
        for (int t2 = 0; t2 < 32; t2++) {
            float4 v = *reinterpret_cast<const float4*>(sp + t2 * 4);
            s = fmaf(v.x, v.x, fmaf(v.y, v.y, fmaf(v.z, v.z, fmaf(v.w, v.w, s))));
        }
        s += __shfl_xor_sync(0xffffffffu, s, 1);
        s += __shfl_xor_sync(0xffffffffu, s, 2);
        if (p == 0) g_w1[j * NL + q] = sqrtf(s);
    }
}

// ===========================================================================
// Kernel C: per-pair epilogue (float4 GEMM2, strides 68)
// ===========================================================================
__global__ __launch_bounds__(256) void pair_kernel(float* __restrict__ out) {
    __shared__ float Ah[64 * 68];
    __shared__ float Gh[64 * 68];
    __shared__ float pbuf[16 * 68];
    __shared__ float colm[64], crZ[64], rowm[64], rrZ[64], esum[64];

    const int i = blockIdx.x, j = blockIdx.y;
    const int tid = threadIdx.x;
    const int tx = tid & 15, ty = tid >> 4;
    const int row0 = ty * 4, col0 = tx * 4;

    float c[4][4];
    const float* Sp = g_S + ((size_t)i * 64) * 4096u + (size_t)j * 64;
#pragma unroll
    for (int m = 0; m < 4; m++) {
        float4 v4 = *reinterpret_cast<const float4*>(Sp + (size_t)(row0 + m) * 4096u + col0);
        c[m][0] = v4.x; c[m][1] = v4.y; c[m][2] = v4.z; c[m][3] = v4.w;
    }
    {
        const float* Gp = g_G + (size_t)j * NL * NL;
        int f = (tid & 15) * 4;
        int q0 = tid >> 4;
#pragma unroll
        for (int r = 0; r < 4; ++r) {
            int q = q0 + r * 16;
            float4 g = *reinterpret_cast<const float4*>(Gp + q * NL + f);
            *reinterpret_cast<float4*>(&Gh[q * 68 + f]) = g;
        }
    }

    // ---- column max ----
#pragma unroll
    for (int n = 0; n < 4; n++) {
        float pm = c[0][n];
#pragma unroll
        for (int m = 1; m < 4; m++) pm = fmaxf(pm, c[m][n]);
        pbuf[ty * 68 + col0 + n] = pm;
    }
    __syncthreads();
    if (tid < 64) {
        float m = -1e30f;
#pragma unroll
        for (int p = 0; p < 16; p++) m = fmaxf(m, pbuf[p * 68 + tid]);
        colm[tid] = m;
    }
    __syncthreads();

    // ---- e1 once; column sums ----
    float v[4][4];
#pragma unroll
    for (int n = 0; n < 4; n++) {
        float cm = colm[col0 + n];
        float s = 0.f;
#pragma unroll
        for (int m = 0; m < 4; m++) {
            float e = fexp(c[m][n] - cm);
            v[m][n] = e;
            s += e;
        }
        pbuf[ty * 68 + col0 + n] = s;
    }
    __syncthreads();
    if (tid < 64) {
        float z = 0.f;
#pragma unroll
        for (int p = 0; p < 16; p++) z += pbuf[p * 68 + tid];
        crZ[tid] = 4.f / z;
    }
    __syncthreads();

    // ---- V = 4*A1^T; row max ----
#pragma unroll
    for (int n = 0; n < 4; n++) {
        float zr = crZ[col0 + n];
#pragma unroll
        for (int m = 0; m < 4; m++) v[m][n] *= zr;
    }
#pragma unroll
    for (int m = 0; m < 4; m++) {
        float pm = v[m][0];
#pragma unroll
        for (int n = 1; n < 4; n++) pm = fmaxf(pm, v[m][n]);
        pbuf[tx * 68 + row0 + m] = pm;
    }
    __syncthreads();
    if (tid < 64) {
        float m = -1e30f;
#pragma unroll
        for (int p = 0; p < 16; p++) m = fmaxf(m, pbuf[p * 68 + tid]);
        rowm[tid] = m;
    }
    __syncthreads();

    // ---- e2 once; row sums ----
#pragma unroll
    for (int m = 0; m < 4; m++) {
        float rm = rowm[row0 + m];
        float s = 0.f;
#pragma unroll
        for (int n = 0; n < 4; n++) {
            float e = fexp(v[m][n] - rm);
            v[m][n] = e;
            s += e;
        }
        pbuf[tx * 68 + row0 + m] = s;
    }
    __syncthreads();
    if (tid < 64) {
        float z = 0.f;
#pragma unroll
        for (int p = 0; p < 16; p++) z += pbuf[p * 68 + tid];
        rrZ[tid] = 1.f / z;
    }
    __syncthreads();

    // ---- A2 ; w12 partials ----
#pragma unroll
    for (int m = 0; m < 4; m++) {
        float zr = rrZ[row0 + m];
        float w12p = 0.f;
#pragma unroll
        for (int n = 0; n < 4; n++) {
            float a2 = v[m][n] * zr;
            v[m][n] = a2;
            w12p = fmaf(a2, c[m][n], w12p);
        }
        pbuf[tx * 68 + row0 + m] = w12p;
    }
    __syncthreads();
    float my_w12 = 0.f;
    if (tid < 64) {
#pragma unroll
        for (int p = 0; p < 16; p++) my_w12 += pbuf[p * 68 + tid];
    }

#pragma unroll
    for (int m = 0; m < 4; m++)
#pragma unroll
        for (int n = 0; n < 4; n++) Ah[(row0 + m) * 68 + col0 + n] = v[m][n];
    __syncthreads();

    // ---- GEMM2 (float4 loads): T = A2 @ G_j ----
    float t4[4][4];
#pragma unroll
    for (int m = 0; m < 4; m++)
#pragma unroll
        for (int n = 0; n < 4; n++) t4[m][n] = 0.f;
#pragma unroll 4
    for (int k4 = 0; k4 < 16; k4++) {
        float4 a4[4], g4[4];
#pragma unroll
        for (int m = 0; m < 4; m++)
            a4[m] = *reinterpret_cast<const float4*>(&Ah[(row0 + m) * 68 + k4 * 4]);
#pragma unroll
        for (int kk = 0; kk < 4; kk++)
            g4[kk] = *reinterpret_cast<const float4*>(&Gh[(k4 * 4 + kk) * 68 + col0]);
#pragma unroll
        for (int m = 0; m < 4; m++) {
            float* tm = t4[m];
            tm[0] = fmaf(a4[m].x, g4[0].x, fmaf(a4[m].y, g4[1].x, fmaf(a4[m].z, g4[2].x, fmaf(a4[m].w, g4[3].x, tm[0]))));
            tm[1] = fmaf(a4[m].x, g4[0].y, fmaf(a4[m].y, g4[1].y, fmaf(a4[m].z, g4[2].y, fmaf(a4[m].w, g4[3].y, tm[1]))));
            tm[2] = fmaf(a4[m].x, g4[0].z, fmaf(a4[m].y, g4[1].z, fmaf(a4[m].z, g4[2].z, fmaf(a4[m].w, g4[3].z, tm[2]))));
            tm[3] = fmaf(a4[m].x, g4[0].w, fmaf(a4[m].y, g4[1].w, fmaf(a4[m].z, g4[2].w, fmaf(a4[m].w, g4[3].w, tm[3]))));
        }
    }
    __syncthreads();
#pragma unroll
    for (int m = 0; m < 4; m++) {
        float w2p = 0.f;
#pragma unroll
        for (int n = 0; n < 4; n++) w2p = fmaf(t4[m][n], v[m][n], w2p);
        pbuf[tx * 68 + row0 + m] = w2p;
    }
    __syncthreads();

    if (tid < 64) {
        float w2sq = 0.f;
#pragma unroll
        for (int p = 0; p < 16; p++) w2sq += pbuf[p * 68 + tid];
        float w2 = sqrtf(fmaxf(w2sq, 0.f));
        float den = fmaxf(g_w1[i * NL + tid] * w2, 1e-8f);
        float cs = my_w12 / den;
        esum[tid] = __expf(5.f * cs);
    }
    __syncthreads();
    if (tid == 0) {
        float z = 0.f;
#pragma unroll
        for (int q = 0; q < 64; q++) z += esum[q];
        g_sim[j * NB + i] = 10.f * logf(z);
    }

    if (i == j) {
        float* ap = out + 1 + (size_t)i * NL * NL;
#pragma unroll
        for (int m = 0; m < 4; m++)
#pragma unroll
            for (int n = 0; n < 4; n++)
                ap[(row0 + m) * NL + col0 + n] = v[m][n];
    }
}

// ===========================================================================
// Kernel D: symmetric InfoNCE loss.
// ===========================================================================
__global__ __launch_bounds__(256) void loss_kernel(float* __restrict__ out) {
    __shared__ float sm[64 * 64];
    __shared__ float sh[64];
    const int tid = threadIdx.x;
#pragma unroll
    for (int r = 0; r < 4; ++r) {
        int idx = tid * 4 + r * 1024;
        *reinterpret_cast<float4*>(sm + idx) = *reinterpret_cast<const float4*>(g_sim + idx);
    }
    __syncthreads();
    if (tid < 64) {
        int t = tid;
        float m1 = -1e30f, m2 = -1e30f;
#pragma unroll 8
        for (int b = 0; b < NB; b++) {
            m1 = fmaxf(m1, sm[t * NB + b]);
            m2 = fmaxf(m2, sm[b * NB + t]);
        }
        float z1 = 0.f, z2 = 0.f;
#pragma unroll 8
        for (int b = 0; b < NB; b++) {
            z1 += fexp(sm[t * NB + b] - m1);
            z2 += fexp(sm[b * NB + t] - m2);
        }
        float dg = sm[t * NB + t];
        sh[t] = (dg - (m1 + logf(z1))) + (dg - (m2 + logf(z2)));
    }
    __syncthreads();
    if (tid == 0) {
        float s = 0.f;
#pragma unroll
        for (int q = 0; q < NB; q++) s += sh[q];
        out[0] = -s / (2.f * (float)NB);
    }
}

extern "C" void kernel_launch(void* const* d_in, const int* in_sizes, int n_in,
                              void* d_out, int out_size) {
    const float* ecg = (const float*)d_in[0];   // (64,64,512)
    const float* sent = (const float*)d_in[1];  // (64,64,512)
    float* out = (float*)d_out;                 // [loss, att_maps]

    cudaFuncSetAttribute(s_gemm_kernel, cudaFuncAttributeMaxDynamicSharedMemorySize, SMEM_TOTAL);

    s_gemm_kernel<<<dim3(32, 32), 256, SMEM_TOTAL>>>(ecg, sent);
    gram_kernel<<<256, 256>>>(ecg, sent);
    pair_kernel<<<dim3(64, 64), 256>>>(out);
    loss_kernel<<<1, 256>>>(out);
}

// round 6
// speedup vs baseline: 1.6126x; 1.4621x over previous
#include <cuda_runtime.h>
#include <cuda_fp16.h>
#include <math.h>
#include <cstdint>

#define NB 64
#define NL 64
#define ND 512

// ---------------- device scratch (allocation-free rule) ----------------
__device__ float g_G[NB * NL * NL];     // Gram per j
__device__ float g_w1[NB * NL];         // ||sent[i,q]||
__device__ float g_sim[NB * NB];        // g_sim[j*64+i]
__device__ float g_S[4096u * 4096u];    // scores

// ---------------- helpers ----------------
__device__ __forceinline__ uint32_t smem_u32(const void* p) {
    uint32_t a;
    asm("{ .reg .u64 t; cvta.to.shared.u64 t, %1; cvt.u32.u64 %0, t; }" : "=r"(a) : "l"(p));
    return a;
}
__device__ __forceinline__ void lds64(uint32_t& x, uint32_t& y, uint32_t a) {
    asm volatile("ld.shared.v2.b32 {%0, %1}, [%2];" : "=r"(x), "=r"(y) : "r"(a));
}
__device__ __forceinline__ void sts128v(uint32_t a, uint32_t x, uint32_t y, uint32_t z, uint32_t w) {
    asm volatile("st.shared.v4.b32 [%0], {%1, %2, %3, %4};"
                 :: "r"(a), "r"(x), "r"(y), "r"(z), "r"(w) : "memory");
}
__device__ __forceinline__ uint32_t pkh(__half a, __half b) {
    __half2 h = __halves2half2(a, b);   // .x = a (low, even k), .y = b (odd k)
    return *reinterpret_cast<uint32_t*>(&h);
}
__device__ __forceinline__ void mma_f16(float* c, const uint32_t* a, const uint32_t* b) {
    asm volatile(
        "mma.sync.aligned.m16n8k16.row.col.f32.f16.f16.f32 "
        "{%0,%1,%2,%3}, {%4,%5,%6,%7}, {%8,%9}, {%0,%1,%2,%3};"
        : "+f"(c[0]), "+f"(c[1]), "+f"(c[2]), "+f"(c[3])
        : "r"(a[0]), "r"(a[1]), "r"(a[2]), "r"(a[3]), "r"(b[0]), "r"(b[1]));
}

// FMA-pipe exp for x <= 0 (clamped at -87), rel err ~1e-7.
__device__ __forceinline__ float fexp(float x) {
    x = fmaxf(x, -87.0f);
    float t = fmaf(x, 1.4426950408889634f, 12582912.0f);
    float n = t - 12582912.0f;
    float f = fmaf(x, 1.4426950408889634f, -n);
    float p = 1.33978935e-3f;
    p = fmaf(p, f, 9.67518295e-3f);
    p = fmaf(p, f, 5.55041086e-2f);
    p = fmaf(p, f, 2.40226507e-1f);
    p = fmaf(p, f, 6.93147182e-1f);
    p = fmaf(p, f, 1.0f);
    int ni = __float_as_int(t) - 0x4B400000;
    float s = __int_as_float((ni + 127) << 23);
    return p * s;
}

// ===========================================================================
// Kernel A: S = sent(4096x512) @ ecg(4096x512)^T via 3xFP16 mma.sync m16n8k16
//   CTA tile 128x128, 8 warps (2M x 4N), warp tile 64x32.
//   Smem: half2 words, row stride 24 words, k16-group offset 12 words,
//   within-group word = 2*(h&3) + (h>>2). LDS.64 & STS.128 conflict-free.
// ===========================================================================
#define BK 32
#define NCH (ND / BK)
#define ROWW 24u                         // words per row
#define TILE_BYTES (128u * ROWW * 4u)    // 12288
#define OFF_AHI 0u
#define OFF_ALO 12288u
#define OFF_BHI 24576u
#define OFF_BLO 36864u
#define STAGE_B 49152u
#define SMEM_TOTAL (2u * STAGE_B)        // 98304

__global__ __launch_bounds__(256, 1) void s_gemm_kernel(const float* __restrict__ ecg,
                                                        const float* __restrict__ sent) {
    extern __shared__ char dsm[];
    const uint32_t sbase = smem_u32(dsm);

    const int tid = threadIdx.x;
    const int wid = tid >> 5, lane = tid & 31;
    const int tileN = blockIdx.x;
    const int tileM = blockIdx.y;

    const int grow = tid >> 1;               // 0..127
    const int g = tid & 1;                   // k16 group
    const float* Ag = sent + ((size_t)tileM * 128 + grow) * ND + g * 16;
    const float* Bg = ecg + ((size_t)tileN * 128 + grow) * ND + g * 16;
    const uint32_t wbB = ((uint32_t)grow * ROWW + (uint32_t)g * 12u) * 4u;  // byte base

    const uint32_t warpM = (uint32_t)(wid & 1) * 64u;
    const uint32_t warpN = (uint32_t)(wid >> 1) * 32u;
    const uint32_t lg = lane >> 2, lt = lane & 3;

    float acc[4][4][4];
#pragma unroll
    for (int mi = 0; mi < 4; ++mi)
#pragma unroll
        for (int ni = 0; ni < 4; ++ni)
#pragma unroll
            for (int r = 0; r < 4; ++r) acc[mi][ni][r] = 0.f;

    float4 ra[4], rb[4];
    auto ldg_chunk = [&](int t) {
#pragma unroll
        for (int r = 0; r < 4; ++r) {
            ra[r] = *reinterpret_cast<const float4*>(Ag + t * BK + r * 4);
            rb[r] = *reinterpret_cast<const float4*>(Bg + t * BK + r * 4);
        }
    };

    // convert 16 floats -> hi/lo half2 words, permuted, 2x stv4 per buffer
    auto cvt_store = [&](const float4* q, uint32_t hiB, uint32_t loB) {
        float v[16];
#pragma unroll
        for (int r = 0; r < 4; ++r) {
            v[r * 4 + 0] = q[r].x; v[r * 4 + 1] = q[r].y;
            v[r * 4 + 2] = q[r].z; v[r * 4 + 3] = q[r].w;
        }
        __half H[16], L[16];
#pragma unroll
        for (int idx = 0; idx < 16; ++idx) {
            __half h = __float2half_rn(v[idx]);
            H[idx] = h;
            L[idx] = __float2half_rn(v[idx] - __half2float(h));
        }
        // word w holds value-pair starting at index pi[w]
        // pi = {0,8,2,10,4,12,6,14}
        uint32_t W0 = pkh(H[0], H[1]), W1 = pkh(H[8], H[9]);
        uint32_t W2 = pkh(H[2], H[3]), W3 = pkh(H[10], H[11]);
        uint32_t W4 = pkh(H[4], H[5]), W5 = pkh(H[12], H[13]);
        uint32_t W6 = pkh(H[6], H[7]), W7 = pkh(H[14], H[15]);
        sts128v(hiB + wbB, W0, W1, W2, W3);
        sts128v(hiB + wbB + 16u, W4, W5, W6, W7);
        uint32_t X0 = pkh(L[0], L[1]), X1 = pkh(L[8], L[9]);
        uint32_t X2 = pkh(L[2], L[3]), X3 = pkh(L[10], L[11]);
        uint32_t X4 = pkh(L[4], L[5]), X5 = pkh(L[12], L[13]);
        uint32_t X6 = pkh(L[6], L[7]), X7 = pkh(L[14], L[15]);
        sts128v(loB + wbB, X0, X1, X2, X3);
        sts128v(loB + wbB + 16u, X4, X5, X6, X7);
    };

    auto sts_chunk = [&](uint32_t st) {
        cvt_store(ra, st + OFF_AHI, st + OFF_ALO);
        cvt_store(rb, st + OFF_BHI, st + OFF_BLO);
    };

    // prologue
    ldg_chunk(0);
    sts_chunk(sbase);
    ldg_chunk(1);
    __syncthreads();

    for (int t = 0; t < NCH; ++t) {
        const uint32_t st = sbase + (uint32_t)(t & 1) * STAGE_B;
        if (t + 1 < NCH) sts_chunk(sbase + (uint32_t)((t + 1) & 1) * STAGE_B);
        if (t + 2 < NCH) ldg_chunk(t + 2);

#pragma unroll
        for (int s = 0; s < 2; ++s) {
            uint32_t ah[4][4], al[4][4], bh[4][2], bl[4][2];
            const uint32_t kw = (uint32_t)s * 12u + 2u * lt;   // word offset
#pragma unroll
            for (int mi = 0; mi < 4; ++mi) {
                uint32_t r0 = (warpM + mi * 16u + lg) * ROWW + kw;
                uint32_t r1 = r0 + 8u * ROWW;
                lds64(ah[mi][0], ah[mi][2], st + OFF_AHI + r0 * 4u);
                lds64(ah[mi][1], ah[mi][3], st + OFF_AHI + r1 * 4u);
                lds64(al[mi][0], al[mi][2], st + OFF_ALO + r0 * 4u);
                lds64(al[mi][1], al[mi][3], st + OFF_ALO + r1 * 4u);
            }
#pragma unroll
            for (int ni = 0; ni < 4; ++ni) {
                uint32_t r0 = (warpN + ni * 8u + lg) * ROWW + kw;
                lds64(bh[ni][0], bh[ni][1], st + OFF_BHI + r0 * 4u);
                lds64(bl[ni][0], bl[ni][1], st + OFF_BLO + r0 * 4u);
            }
#pragma unroll
            for (int mi = 0; mi < 4; ++mi)
#pragma unroll
                for (int ni = 0; ni < 4; ++ni) {
                    mma_f16(acc[mi][ni], ah[mi], bh[ni]);
                    mma_f16(acc[mi][ni], ah[mi], bl[ni]);
                    mma_f16(acc[mi][ni], al[mi], bh[ni]);
                }
        }
        __syncthreads();
    }

    const size_t rbase = (size_t)tileM * 128 + warpM + lg;
    const size_t cbase = (size_t)tileN * 128 + warpN + lt * 2;
#pragma unroll
    for (int mi = 0; mi < 4; ++mi)
#pragma unroll
        for (int ni = 0; ni < 4; ++ni) {
            float* p0 = g_S + (rbase + mi * 16) * 4096u + cbase + ni * 8;
            *reinterpret_cast<float2*>(p0) = make_float2(acc[mi][ni][0], acc[mi][ni][1]);
            *reinterpret_cast<float2*>(p0 + 8 * 4096u) = make_float2(acc[mi][ni][2], acc[mi][ni][3]);
        }
}

// ===========================================================================
// Kernel B: Gram quadrants (256 CTAs) + w1 norms. (unchanged)
// ===========================================================================
__global__ __launch_bounds__(256) void gram_kernel(const float* __restrict__ ecg,
                                                   const float* __restrict__ sent) {
    __shared__ float sA[32 * 66];
    __shared__ float sB[32 * 66];
    const int j = blockIdx.x >> 2;
    const int quad = blockIdx.x & 3;
    const int qr = (quad >> 1) * 32, qc = (quad & 1) * 32;
    const int tid = threadIdx.x;
    const int tx = tid & 15, ty = tid >> 4;
    const int r0 = ty * 2, c0 = tx * 2;
    const float* base = ecg + (size_t)j * NL * ND;

    float c00 = 0.f, c01 = 0.f, c10 = 0.f, c11 = 0.f;
    const int lrow = tid >> 3;
    const int lcol = (tid & 7) * 8;

    for (int kt = 0; kt < ND; kt += 64) {
        __syncthreads();
#pragma unroll
        for (int r = 0; r < 2; ++r) {
            float4 va = *reinterpret_cast<const float4*>(base + (qr + lrow) * ND + kt + lcol + r * 4);
            sA[lrow * 66 + lcol + r * 4 + 0] = va.x;
            sA[lrow * 66 + lcol + r * 4 + 1] = va.y;
            sA[lrow * 66 + lcol + r * 4 + 2] = va.z;
            sA[lrow * 66 + lcol + r * 4 + 3] = va.w;
            float4 vb = *reinterpret_cast<const float4*>(base + (qc + lrow) * ND + kt + lcol + r * 4);
            sB[lrow * 66 + lcol + r * 4 + 0] = vb.x;
            sB[lrow * 66 + lcol + r * 4 + 1] = vb.y;
            sB[lrow * 66 + lcol + r * 4 + 2] = vb.z;
            sB[lrow * 66 + lcol + r * 4 + 3] = vb.w;
        }
        __syncthreads();
#pragma unroll 8
        for (int k = 0; k < 64; ++k) {
            float a0 = sA[r0 * 66 + k], a1 = sA[(r0 + 1) * 66 + k];
            float b0 = sB[c0 * 66 + k], b1 = sB[(c0 + 1) * 66 + k];
            c00 = fmaf(a0, b0, c00);
            c01 = fmaf(a0, b1, c01);
            c10 = fmaf(a1, b0, c10);
            c11 = fmaf(a1, b1, c11);
        }
    }
    float* Gp = g_G + (size_t)j * NL * NL;
    Gp[(qr + r0) * NL + qc + c0] = c00;
    Gp[(qr + r0) * NL + qc + c0 + 1] = c01;
    Gp[(qr + r0 + 1) * NL + qc + c0] = c10;
    Gp[(qr + r0 + 1) * NL + qc + c0 + 1] = c11;

    if (quad == 0) {
        int q = tid >> 2;
        int p = tid & 3;
        const float* sp = sent + (size_t)j * NL * ND + q * ND + p * 128;
        float s = 0.f;
#pragma unroll 8
        for (int t2 = 0; t2 < 32; t2++) {
            float4 v = *reinterpret_cast<const float4*>(sp + t2 * 4);
            s = fmaf(v.x, v.x, fmaf(v.y, v.y, fmaf(v.z, v.z, fmaf(v.w, v.w, s))));
        }
        s += __shfl_xor_sync(0xffffffffu, s, 1);
        s += __shfl_xor_sync(0xffffffffu, s, 2);
        if (p == 0) g_w1[j * NL + q] = sqrtf(s);
    }
}

// ===========================================================================
// Kernel C: per-pair epilogue (unchanged from R5)
// ===========================================================================
__global__ __launch_bounds__(256) void pair_kernel(float* __restrict__ out) {
    __shared__ float Ah[64 * 68];
    __shared__ float Gh[64 * 68];
    __shared__ float pbuf[16 * 68];
    __shared__ float colm[64], crZ[64], rowm[64], rrZ[64], esum[64];

    const int i = blockIdx.x, j = blockIdx.y;
    const int tid = threadIdx.x;
    const int tx = tid & 15, ty = tid >> 4;
    const int row0 = ty * 4, col0 = tx * 4;

    float c[4][4];
    const float* Sp = g_S + ((size_t)i * 64) * 4096u + (size_t)j * 64;
#pragma unroll
    for (int m = 0; m < 4; m++) {
        float4 v4 = *reinterpret_cast<const float4*>(Sp + (size_t)(row0 + m) * 4096u + col0);
        c[m][0] = v4.x; c[m][1] = v4.y; c[m][2] = v4.z; c[m][3] = v4.w;
    }
    {
        const float* Gp = g_G + (size_t)j * NL * NL;
        int f = (tid & 15) * 4;
        int q0 = tid >> 4;
#pragma unroll
        for (int r = 0; r < 4; ++r) {
            int q = q0 + r * 16;
            float4 gg = *reinterpret_cast<const float4*>(Gp + q * NL + f);
            *reinterpret_cast<float4*>(&Gh[q * 68 + f]) = gg;
        }
    }

#pragma unroll
    for (int n = 0; n < 4; n++) {
        float pm = c[0][n];
#pragma unroll
        for (int m = 1; m < 4; m++) pm = fmaxf(pm, c[m][n]);
        pbuf[ty * 68 + col0 + n] = pm;
    }
    __syncthreads();
    if (tid < 64) {
        float m = -1e30f;
#pragma unroll
        for (int p = 0; p < 16; p++) m = fmaxf(m, pbuf[p * 68 + tid]);
        colm[tid] = m;
    }
    __syncthreads();

    float v[4][4];
#pragma unroll
    for (int n = 0; n < 4; n++) {
        float cm = colm[col0 + n];
        float s = 0.f;
#pragma unroll
        for (int m = 0; m < 4; m++) {
            float e = fexp(c[m][n] - cm);
            v[m][n] = e;
            s += e;
        }
        pbuf[ty * 68 + col0 + n] = s;
    }
    __syncthreads();
    if (tid < 64) {
        float z = 0.f;
#pragma unroll
        for (int p = 0; p < 16; p++) z += pbuf[p * 68 + tid];
        crZ[tid] = 4.f / z;
    }
    __syncthreads();

#pragma unroll
    for (int n = 0; n < 4; n++) {
        float zr = crZ[col0 + n];
#pragma unroll
        for (int m = 0; m < 4; m++) v[m][n] *= zr;
    }
#pragma unroll
    for (int m = 0; m < 4; m++) {
        float pm = v[m][0];
#pragma unroll
        for (int n = 1; n < 4; n++) pm = fmaxf(pm, v[m][n]);
        pbuf[tx * 68 + row0 + m] = pm;
    }
    __syncthreads();
    if (tid < 64) {
        float m = -1e30f;
#pragma unroll
        for (int p = 0; p < 16; p++) m = fmaxf(m, pbuf[p * 68 + tid]);
        rowm[tid] = m;
    }
    __syncthreads();

#pragma unroll
    for (int m = 0; m < 4; m++) {
        float rm = rowm[row0 + m];
        float s = 0.f;
#pragma unroll
        for (int n = 0; n < 4; n++) {
            float e = fexp(v[m][n] - rm);
            v[m][n] = e;
            s += e;
        }
        pbuf[tx * 68 + row0 + m] = s;
    }
    __syncthreads();
    if (tid < 64) {
        float z = 0.f;
#pragma unroll
        for (int p = 0; p < 16; p++) z += pbuf[p * 68 + tid];
        rrZ[tid] = 1.f / z;
    }
    __syncthreads();

#pragma unroll
    for (int m = 0; m < 4; m++) {
        float zr = rrZ[row0 + m];
        float w12p = 0.f;
#pragma unroll
        for (int n = 0; n < 4; n++) {
            float a2 = v[m][n] * zr;
            v[m][n] = a2;
            w12p = fmaf(a2, c[m][n], w12p);
        }
        pbuf[tx * 68 + row0 + m] = w12p;
    }
    __syncthreads();
    float my_w12 = 0.f;
    if (tid < 64) {
#pragma unroll
        for (int p = 0; p < 16; p++) my_w12 += pbuf[p * 68 + tid];
    }

#pragma unroll
    for (int m = 0; m < 4; m++)
#pragma unroll
        for (int n = 0; n < 4; n++) Ah[(row0 + m) * 68 + col0 + n] = v[m][n];
    __syncthreads();

    float t4[4][4];
#pragma unroll
    for (int m = 0; m < 4; m++)
#pragma unroll
        for (int n = 0; n < 4; n++) t4[m][n] = 0.f;
#pragma unroll 4
    for (int k4 = 0; k4 < 16; k4++) {
        float4 a4[4], g4[4];
#pragma unroll
        for (int m = 0; m < 4; m++)
            a4[m] = *reinterpret_cast<const float4*>(&Ah[(row0 + m) * 68 + k4 * 4]);
#pragma unroll
        for (int kk = 0; kk < 4; kk++)
            g4[kk] = *reinterpret_cast<const float4*>(&Gh[(k4 * 4 + kk) * 68 + col0]);
#pragma unroll
        for (int m = 0; m < 4; m++) {
            float* tm = t4[m];
            tm[0] = fmaf(a4[m].x, g4[0].x, fmaf(a4[m].y, g4[1].x, fmaf(a4[m].z, g4[2].x, fmaf(a4[m].w, g4[3].x, tm[0]))));
            tm[1] = fmaf(a4[m].x, g4[0].y, fmaf(a4[m].y, g4[1].y, fmaf(a4[m].z, g4[2].y, fmaf(a4[m].w, g4[3].y, tm[1]))));
            tm[2] = fmaf(a4[m].x, g4[0].z, fmaf(a4[m].y, g4[1].z, fmaf(a4[m].z, g4[2].z, fmaf(a4[m].w, g4[3].z, tm[2]))));
            tm[3] = fmaf(a4[m].x, g4[0].w, fmaf(a4[m].y, g4[1].w, fmaf(a4[m].z, g4[2].w, fmaf(a4[m].w, g4[3].w, tm[3]))));
        }
    }
    __syncthreads();
#pragma unroll
    for (int m = 0; m < 4; m++) {
        float w2p = 0.f;
#pragma unroll
        for (int n = 0; n < 4; n++) w2p = fmaf(t4[m][n], v[m][n], w2p);
        pbuf[tx * 68 + row0 + m] = w2p;
    }
    __syncthreads();

    if (tid < 64) {
        float w2sq = 0.f;
#pragma unroll
        for (int p = 0; p < 16; p++) w2sq += pbuf[p * 68 + tid];
        float w2 = sqrtf(fmaxf(w2sq, 0.f));
        float den = fmaxf(g_w1[i * NL + tid] * w2, 1e-8f);
        float cs = my_w12 / den;
        esum[tid] = __expf(5.f * cs);
    }
    __syncthreads();
    if (tid == 0) {
        float z = 0.f;
#pragma unroll
        for (int q = 0; q < 64; q++) z += esum[q];
        g_sim[j * NB + i] = 10.f * logf(z);
    }

    if (i == j) {
        float* ap = out + 1 + (size_t)i * NL * NL;
#pragma unroll
        for (int m = 0; m < 4; m++)
#pragma unroll
            for (int n = 0; n < 4; n++)
                ap[(row0 + m) * NL + col0 + n] = v[m][n];
    }
}

// ===========================================================================
// Kernel D: symmetric InfoNCE loss. (unchanged)
// ===========================================================================
__global__ __launch_bounds__(256) void loss_kernel(float* __restrict__ out) {
    __shared__ float sm[64 * 64];
    __shared__ float sh[64];
    const int tid = threadIdx.x;
#pragma unroll
    for (int r = 0; r < 4; ++r) {
        int idx = tid * 4 + r * 1024;
        *reinterpret_cast<float4*>(sm + idx) = *reinterpret_cast<const float4*>(g_sim + idx);
    }
    __syncthreads();
    if (tid < 64) {
        int t = tid;
        float m1 = -1e30f, m2 = -1e30f;
#pragma unroll 8
        for (int b = 0; b < NB; b++) {
            m1 = fmaxf(m1, sm[t * NB + b]);
            m2 = fmaxf(m2, sm[b * NB + t]);
        }
        float z1 = 0.f, z2 = 0.f;
#pragma unroll 8
        for (int b = 0; b < NB; b++) {
            z1 += fexp(sm[t * NB + b] - m1);
            z2 += fexp(sm[b * NB + t] - m2);
        }
        float dg = sm[t * NB + t];
        sh[t] = (dg - (m1 + logf(z1))) + (dg - (m2 + logf(z2)));
    }
    __syncthreads();
    if (tid == 0) {
        float s = 0.f;
#pragma unroll
        for (int q = 0; q < NB; q++) s += sh[q];
        out[0] = -s / (2.f * (float)NB);
    }
}

extern "C" void kernel_launch(void* const* d_in, const int* in_sizes, int n_in,
                              void* d_out, int out_size) {
    const float* ecg = (const float*)d_in[0];   // (64,64,512)
    const float* sent = (const float*)d_in[1];  // (64,64,512)
    float* out = (float*)d_out;                 // [loss, att_maps]

    cudaFuncSetAttribute(s_gemm_kernel, cudaFuncAttributeMaxDynamicSharedMemorySize, SMEM_TOTAL);

    s_gemm_kernel<<<dim3(32, 32), 256, SMEM_TOTAL>>>(ecg, sent);
    gram_kernel<<<256, 256>>>(ecg, sent);
    pair_kernel<<<dim3(64, 64), 256>>>(out);
    loss_kernel<<<1, 256>>>(out);
}